// round 11
// baseline (speedup 1.0000x reference)
#include <cuda_runtime.h>
#include <cstdint>

#define KK 64

__device__ __forceinline__ float fast_rcp(float x) {
    float r; asm("rcp.approx.f32 %0, %1;" : "=f"(r) : "f"(x)); return r;
}

__device__ __forceinline__ uint32_t smem_u32(const void* p) {
    uint32_t a;
    asm("{ .reg .u64 t; cvta.to.shared.u64 t, %1; cvt.u32.u64 %0, t; }"
        : "=r"(a) : "l"(p));
    return a;
}

// TWO INTERLEAVED BATCH CHAINS PER 2-WARP BLOCK (64 threads; thread s owns
// state s of BOTH batches). The two dot products per round are independent,
// so chain B's instructions issue while chain A's LDS->FMA chain is in
// flight (ILP against the latency wall: steps are ~80% stall, fma=16.7%).
// One bar.sync per round serves both chains. M registers are shared (they
// depend only on the output state). grid = B/2 = 128 <= 148 SMs.
//   u_t = (u_{t-1} . M) * exp(emit_t)        (masked steps: u_t = u_{t-1})
//   every 8th step (unconditional): u *= 1/u[0], C += log(u[0])
//   log_Z = C + log(sum_j u_T[j])
__global__ __launch_bounds__(KK, 1) void crf_forward_kernel(
    const int* __restrict__ y, const float* __restrict__ em,
    const float* __restrict__ tr, int Tn, float negInvB,
    float* __restrict__ out)
{
    __shared__ __align__(16) float u_sh[2][2][KK];   // [chain][buf][state]
    __shared__ int yA_sh[1024], yB_sh[1024];         // T = 1024
    __shared__ float red4[4];                        // [chain*2 + warp]

    const int s = threadIdx.x;           // state index 0..63
    const int l = threadIdx.x & 31;
    const int bA = blockIdx.x * 2;
    const int bB = bA + 1;
    const float* ebA = em + (size_t)bA * Tn * KK;
    const float* ebB = em + (size_t)bB * Tn * KK;

    // Packed M row for state s (shared by both chains):
    //   Mp[q] = (exp(tr[2q][s]), exp(tr[2q+1][s]))
    unsigned long long Mp[32];
#pragma unroll
    for (int q = 0; q < 32; q++) {
        float m0 = __expf(tr[(2 * q) * KK + s]);
        float m1 = __expf(tr[(2 * q + 1) * KK + s]);
        asm("mov.b64 %0, {%1, %2};" : "=l"(Mp[q]) : "f"(m0), "f"(m1));
    }

    // stage y rows in shared
    {
        const int* yA = y + (size_t)bA * Tn;
        const int* yB = y + (size_t)bB * Tn;
        for (int t = s; t < Tn; t += KK) { yA_sh[t] = yA[t]; yB_sh[t] = yB[t]; }
    }

    // u0 = exp(emissions[:,0,:]); own values kept in registers too
    float uownA = __expf(ebA[s]);
    float uownB = __expf(ebB[s]);
    u_sh[0][0][s] = uownA;
    u_sh[1][0][s] = uownB;
    float CA = 0.f, CB = 0.f;
    __syncthreads();

    const uint32_t ubaseA = smem_u32(&u_sh[0][0][0]);
    const uint32_t ubaseB = ubaseA + 512;            // chain stride = 2*64*4
    const uint32_t ustA = ubaseA + (uint32_t)(s << 2);
    const uint32_t ustB = ubaseB + (uint32_t)(s << 2);
    const float* epA = ebA + s;
    const float* epB = ebB + s;

    // One round = one step of BOTH chains. PSRC/RESC compile-time in the hot
    // loop. Shared loads/stores are asm volatile: prevents cross-step CSE of
    // textually identical unrolled bodies (the R4/R5 bug) and pins ordering.
    auto step = [&](float eA, float eB, int tt, int psrc, bool resc) {
        const int ytA = yA_sh[tt];
        const int ytB = yB_sh[tt];
        float exA = __expf(eA);
        float exB = __expf(eB);
        float scA = 1.f, scB = 1.f;
        if (resc) {                       // unconditional rescale (valid always)
            float x0A, x0B;
            asm volatile("ld.shared.f32 %0, [%1];"
                         : "=f"(x0A) : "r"(ubaseA + (uint32_t)(psrc << 8)));
            asm volatile("ld.shared.f32 %0, [%1];"
                         : "=f"(x0B) : "r"(ubaseB + (uint32_t)(psrc << 8)));
            scA = fast_rcp(x0A);  CA += __logf(x0A);
            scB = fast_rcp(x0B);  CB += __logf(x0B);
        }
        const float kA = exA * scA;       // off the u-dependency chains
        const float kB = exB * scB;
        const uint32_t uaA = ubaseA + (uint32_t)(psrc << 8);
        const uint32_t uaB = ubaseB + (uint32_t)(psrc << 8);
        unsigned long long A0 = 0, A1 = 0, A2 = 0, A3 = 0;
        unsigned long long B0 = 0, B1 = 0, B2 = 0, B3 = 0;
#pragma unroll
        for (int g = 0; g < 8; g++) {
            unsigned long long a0, a1, a2, a3, b0, b1, b2, b3;
            asm volatile("ld.shared.v2.u64 {%0, %1}, [%2];"
                : "=l"(a0), "=l"(a1) : "r"(uaA + g * 32));
            asm volatile("ld.shared.v2.u64 {%0, %1}, [%2];"
                : "=l"(b0), "=l"(b1) : "r"(uaB + g * 32));
            asm volatile("ld.shared.v2.u64 {%0, %1}, [%2];"
                : "=l"(a2), "=l"(a3) : "r"(uaA + g * 32 + 16));
            asm volatile("ld.shared.v2.u64 {%0, %1}, [%2];"
                : "=l"(b2), "=l"(b3) : "r"(uaB + g * 32 + 16));
            asm("fma.rn.f32x2 %0, %1, %2, %0;" : "+l"(A0) : "l"(a0), "l"(Mp[4 * g + 0]));
            asm("fma.rn.f32x2 %0, %1, %2, %0;" : "+l"(B0) : "l"(b0), "l"(Mp[4 * g + 0]));
            asm("fma.rn.f32x2 %0, %1, %2, %0;" : "+l"(A1) : "l"(a1), "l"(Mp[4 * g + 1]));
            asm("fma.rn.f32x2 %0, %1, %2, %0;" : "+l"(B1) : "l"(b1), "l"(Mp[4 * g + 1]));
            asm("fma.rn.f32x2 %0, %1, %2, %0;" : "+l"(A2) : "l"(a2), "l"(Mp[4 * g + 2]));
            asm("fma.rn.f32x2 %0, %1, %2, %0;" : "+l"(B2) : "l"(b2), "l"(Mp[4 * g + 2]));
            asm("fma.rn.f32x2 %0, %1, %2, %0;" : "+l"(A3) : "l"(a3), "l"(Mp[4 * g + 3]));
            asm("fma.rn.f32x2 %0, %1, %2, %0;" : "+l"(B3) : "l"(b3), "l"(Mp[4 * g + 3]));
        }
        asm("add.rn.f32x2 %0, %0, %1;" : "+l"(A0) : "l"(A2));
        asm("add.rn.f32x2 %0, %0, %1;" : "+l"(B0) : "l"(B2));
        asm("add.rn.f32x2 %0, %0, %1;" : "+l"(A1) : "l"(A3));
        asm("add.rn.f32x2 %0, %0, %1;" : "+l"(B1) : "l"(B3));
        asm("add.rn.f32x2 %0, %0, %1;" : "+l"(A0) : "l"(A1));
        asm("add.rn.f32x2 %0, %0, %1;" : "+l"(B0) : "l"(B1));
        float alo, ahi, blo, bhi;
        asm("mov.b64 {%0, %1}, %2;" : "=f"(alo), "=f"(ahi) : "l"(A0));
        asm("mov.b64 {%0, %1}, %2;" : "=f"(blo), "=f"(bhi) : "l"(B0));
        float dA = (alo + ahi) * kA;
        float dB = (blo + bhi) * kB;
        // branchless commits (no BSSY/BSYNC in the hot loop)
        uownA = (ytA != 0) ? dA : uownA * scA;
        uownB = (ytB != 0) ? dB : uownB * scB;
        asm volatile("st.shared.f32 [%0], %1;"
                     :: "r"(ustA + (uint32_t)((psrc ^ 1) << 8)), "f"(uownA));
        asm volatile("st.shared.f32 [%0], %1;"
                     :: "r"(ustB + (uint32_t)((psrc ^ 1) << 8)), "f"(uownB));
        __syncthreads();
    };

    const int lim = Tn - 1;               // 1023
    auto eldA = [&](int t) { return epA[(size_t)t * KK]; };
    auto eldB = [&](int t) { return epB[(size_t)t * KK]; };

    // prefetch rows t .. t+3 per chain (depth 4 rounds ≈ 640+ cyc of cover)
    float a0 = eldA(1), a1 = eldA(2), a2 = eldA(3), a3 = eldA(4);
    float b0 = eldB(1), b1 = eldB(2), b2 = eldB(3), b3 = eldB(4);

    int t = 1;
    // main loop: t ≡ 1 (mod 4); parity at entry alternates per 4-block;
    // rescale when (tt & 7) == 0, i.e. at t+3 of every other 4-block.
    int p = 0;
    for (; t + 7 <= lim; t += 4) {
        float nA0 = eldA(t + 4), nA1 = eldA(t + 5), nA2 = eldA(t + 6), nA3 = eldA(t + 7);
        float nB0 = eldB(t + 4), nB1 = eldB(t + 5), nB2 = eldB(t + 6), nB3 = eldB(t + 7);
        if (p == 0) {
            step(a0, b0, t,     0, false);
            step(a1, b1, t + 1, 1, false);
            step(a2, b2, t + 2, 0, false);
            step(a3, b3, t + 3, 1, ((t + 3) & 7) == 0);
        } else {
            step(a0, b0, t,     1, false);
            step(a1, b1, t + 1, 0, false);
            step(a2, b2, t + 2, 1, false);
            step(a3, b3, t + 3, 0, ((t + 3) & 7) == 0);
        }
        a0 = nA0; a1 = nA1; a2 = nA2; a3 = nA3;
        b0 = nB0; b1 = nB1; b2 = nB2; b3 = nB3;
        // p unchanged: 4 steps flip parity 4 times -> net 0
    }

    // tail: runtime parity / rescale; shift-register prefetch, clamped loads
    for (; t <= lim; t++) {
        float nA = eldA(min(t + 4, lim));
        float nB = eldB(min(t + 4, lim));
        step(a0, b0, t, p, (t & 7) == 0);
        p ^= 1;
        a0 = a1; a1 = a2; a2 = a3; a3 = nA;
        b0 = b1; b1 = b2; b2 = b3; b3 = nB;
    }
    // final buffer parity: lim steps total from parity 0
    const int pf = lim & 1;

    // (last step ended with __syncthreads; both u buffers visible)

    // log_Z per chain (redundant per-thread; identical result)
    float sA = 0.f, sB = 0.f;
    const float4* ufA = reinterpret_cast<const float4*>(&u_sh[0][pf][0]);
    const float4* ufB = reinterpret_cast<const float4*>(&u_sh[1][pf][0]);
#pragma unroll
    for (int q = 0; q < KK / 4; q++) {
        float4 ua = ufA[q];  sA += (ua.x + ua.y) + (ua.z + ua.w);
        float4 ub = ufB[q];  sB += (ub.x + ub.y) + (ub.z + ub.w);
    }
    float logzA = CA + __logf(sA);
    float logzB = CB + __logf(sB);

    // numerators: emission + transition scores along the gold paths (masked)
    float numA = 0.f, numB = 0.f;
    for (int tt = s; tt < Tn; tt += KK) {
        int ytA = yA_sh[tt];
        if (ytA != 0) {
            numA += ebA[(size_t)tt * KK + ytA];
            if (tt > 0) numA += tr[yA_sh[tt - 1] * KK + ytA];
        }
        int ytB = yB_sh[tt];
        if (ytB != 0) {
            numB += ebB[(size_t)tt * KK + ytB];
            if (tt > 0) numB += tr[yB_sh[tt - 1] * KK + ytB];
        }
    }
#pragma unroll
    for (int o = 16; o > 0; o >>= 1) {
        numA += __shfl_xor_sync(0xffffffffu, numA, o);
        numB += __shfl_xor_sync(0xffffffffu, numB, o);
    }
    if (l == 0) {
        red4[(s >> 5)] = numA;             // warps 0,1 -> slots 0,1
        red4[2 + (s >> 5)] = numB;         // warps 0,1 -> slots 2,3
    }
    __syncthreads();
    if (s == 0) {
        float llA = (red4[0] + red4[1]) - logzA;
        float llB = (red4[2] + red4[3]) - logzB;
        atomicAdd(out, (llA + llB) * negInvB);   // out pre-zeroed via memset
    }
}

extern "C" void kernel_launch(void* const* d_in, const int* in_sizes, int n_in,
                              void* d_out, int out_size)
{
    const int*   y  = (const int*)d_in[0];
    const float* em = (const float*)d_in[1];
    const float* tr = (const float*)d_in[2];

    const int Tn = 1024;                 // problem shape: B=256, T=1024, K=64
    const int B  = in_sizes[0] / Tn;

    cudaMemsetAsync(d_out, 0, sizeof(float));
    crf_forward_kernel<<<B / 2, KK>>>(y, em, tr, Tn, -1.0f / (float)B,
                                      (float*)d_out);
}

// round 12
// speedup vs baseline: 1.7246x; 1.7246x over previous
#include <cuda_runtime.h>
#include <cstdint>

#define KK 64
#define BUFB 288   // padded u-buffer stride in bytes: 32 floats | 16B pad | 32 floats | 16B pad

__device__ __forceinline__ float fast_rcp(float x) {
    float r; asm("rcp.approx.f32 %0, %1;" : "=f"(r) : "f"(x)); return r;
}

__device__ __forceinline__ uint32_t smem_u32(const void* p) {
    uint32_t a;
    asm("{ .reg .u64 t; cvta.to.shared.u64 t, %1; cvt.u32.u64 %0, t; }"
        : "=r"(a) : "l"(p));
    return a;
}

// ONE BLOCK (2 warps, 64 threads) PER BATCH — R8 geometry, half-u work split.
// Warp w owns output states s = 2l + w. Each thread loads only ONE HALF of u
// (lanes 0-15 -> u[0:32), lanes 16-31 -> u[32:64); 8 LDS.128 instead of 16)
// and computes partial dots for TWO outputs (its own s and partner (l^16)'s)
// over that half — same 32 FFMA2 as before. The missing half-partial arrives
// via one intra-warp shfl.xor(16); barrier structure identical to R8.
// The u halves are stored 16B apart (BUFB padding) so the two concurrent
// half-warp broadcasts hit disjoint banks.
//   u_t = (u_{t-1} . M) * exp(emit_t)        (masked steps: u_t = u_{t-1})
//   every 8th step (unconditional): u *= 1/u[0], C += log(u[0])
//   log_Z = C + log(sum_j u_T[j])
__global__ __launch_bounds__(KK, 1) void crf_forward_kernel(
    const int* __restrict__ y, const float* __restrict__ em,
    const float* __restrict__ tr, int Tn, float negInvB,
    float* __restrict__ out)
{
    __shared__ __align__(128) float u_sh[2][BUFB / 4]; // [buf][padded states]
    __shared__ int y_sh[1024];                         // T = 1024
    __shared__ float red2[2];

    const int tid = threadIdx.x;
    const int w = tid >> 5;               // warp
    const int l = tid & 31;               // lane
    const int h = (l >> 4) & 1;           // which u-half this thread loads
    const int so = 2 * l + w;             // own output state
    const int sp = 2 * (l ^ 16) + w;      // partner's output state
    const int b = blockIdx.x;
    const int* yb = y + (size_t)b * Tn;
    const float* eb = em + (size_t)b * Tn * KK;

    // padded float index for state s: halves 16B apart
    auto pidx = [](int s) { return s + ((s >= 32) ? 4 : 0); };

    // M pairs over MY half of rows, for my output and my partner's output:
    //   MpO[k] = (exp(tr[32h+2k][so]), exp(tr[32h+2k+1][so])), k = 0..15
    unsigned long long MpO[16], MpP[16];
#pragma unroll
    for (int k = 0; k < 16; k++) {
        const int r0 = (32 * h + 2 * k) * KK;
        float o0 = __expf(tr[r0 + so]);
        float o1 = __expf(tr[r0 + KK + so]);
        float p0 = __expf(tr[r0 + sp]);
        float p1 = __expf(tr[r0 + KK + sp]);
        asm("mov.b64 %0, {%1, %2};" : "=l"(MpO[k]) : "f"(o0), "f"(o1));
        asm("mov.b64 %0, {%1, %2};" : "=l"(MpP[k]) : "f"(p0), "f"(p1));
    }

    // stage y row in shared (cooperative)
    for (int t = tid; t < Tn; t += KK) y_sh[t] = yb[t];

    // u0 = exp(emissions[b,0,:]); own value kept in a register too
    float uown = __expf(eb[so]);
    u_sh[0][pidx(so)] = uown;
    float C = 0.f;
    __syncthreads();

    const uint32_t ubase = smem_u32(&u_sh[0][0]);
    const uint32_t uld0  = ubase + (uint32_t)(h * 144);      // my half base
    const uint32_t ust   = ubase + (uint32_t)(pidx(so) << 2);
    const float* ep = eb + so;

    // One recursion step. PSRC/RESC compile-time in the hot loop.
    // Shared loads/stores are asm volatile: prevents cross-step CSE of the
    // textually-identical unrolled bodies (the R4/R5 bug) and pins ordering.
    auto step = [&](float ecur, int tt, int psrc, bool resc) {
        const int yt = y_sh[tt];
        float ex = __expf(ecur);
        float sc = 1.f;
        if (resc) {                       // unconditional rescale (valid always)
            float x0;
            asm volatile("ld.shared.f32 %0, [%1];"
                         : "=f"(x0) : "r"(ubase + (uint32_t)(psrc * BUFB)));
            sc = fast_rcp(x0);
            C += __logf(x0);
        }
        const float k = ex * sc;          // off the u-dependency chain
        const uint32_t ua = uld0 + (uint32_t)(psrc * BUFB);
        unsigned long long A0 = 0, A1 = 0, B0 = 0, B1 = 0;
#pragma unroll
        for (int i = 0; i < 8; i++) {     // my 32 u values, 4 per chunk
            unsigned long long q0, q1;    // (u[.4i],u[.4i+1]), (u[.4i+2],u[.4i+3])
            asm volatile("ld.shared.v2.u64 {%0, %1}, [%2];"
                : "=l"(q0), "=l"(q1) : "r"(ua + i * 16));
            asm("fma.rn.f32x2 %0, %1, %2, %0;" : "+l"(A0) : "l"(q0), "l"(MpO[2 * i]));
            asm("fma.rn.f32x2 %0, %1, %2, %0;" : "+l"(A1) : "l"(q1), "l"(MpO[2 * i + 1]));
            asm("fma.rn.f32x2 %0, %1, %2, %0;" : "+l"(B0) : "l"(q0), "l"(MpP[2 * i]));
            asm("fma.rn.f32x2 %0, %1, %2, %0;" : "+l"(B1) : "l"(q1), "l"(MpP[2 * i + 1]));
        }
        asm("add.rn.f32x2 %0, %0, %1;" : "+l"(A0) : "l"(A1));
        asm("add.rn.f32x2 %0, %0, %1;" : "+l"(B0) : "l"(B1));
        float alo, ahi, blo, bhi;
        asm("mov.b64 {%0, %1}, %2;" : "=f"(alo), "=f"(ahi) : "l"(A0));
        asm("mov.b64 {%0, %1}, %2;" : "=f"(blo), "=f"(bhi) : "l"(B0));
        float PA = alo + ahi;             // my half, my output
        float PB = blo + bhi;             // my half, partner's output
        float PBr = __shfl_xor_sync(0xffffffffu, PB, 16);  // other half, my output
        float dx = (PA + PBr) * k;
        // branchless commit (no BSSY/BSYNC in the hot loop)
        uown = (yt != 0) ? dx : uown * sc;
        asm volatile("st.shared.f32 [%0], %1;"
                     :: "r"(ust + (uint32_t)((psrc ^ 1) * BUFB)), "f"(uown));
        __syncthreads();
    };

    const int lim = Tn - 1;               // 1023
    auto eld = [&](int t) { return ep[(size_t)t * KK]; };

    // prefetch rows t .. t+7 (no clamps needed: lim >= 8 here)
    float e0 = eld(1), e1 = eld(2), e2 = eld(3), e3 = eld(4);
    float e4 = eld(5), e5 = eld(6), e6 = eld(7), e7 = eld(8);

    int t = 1;
    // main loop: t ≡ 1 (mod 8); parity at entry always 0; rescale at t+7 (≡0 mod 8)
    for (; t + 15 <= lim; t += 8) {
        float n0 = eld(t + 8),  n1 = eld(t + 9),  n2 = eld(t + 10), n3 = eld(t + 11);
        float n4 = eld(t + 12), n5 = eld(t + 13), n6 = eld(t + 14), n7 = eld(t + 15);
        step(e0, t,     0, false);
        step(e1, t + 1, 1, false);
        step(e2, t + 2, 0, false);
        step(e3, t + 3, 1, false);
        step(e4, t + 4, 0, false);
        step(e5, t + 5, 1, false);
        step(e6, t + 6, 0, false);
        step(e7, t + 7, 1, true);
        e0 = n0; e1 = n1; e2 = n2; e3 = n3;
        e4 = n4; e5 = n5; e6 = n6; e7 = n7;
    }

    // tail: runtime parity / rescale; shift-register prefetch with clamped loads
    int p = 0;                             // (t-1) is a multiple of 8 here
    for (; t <= lim; t++) {
        float nn = eld(min(t + 8, lim));
        step(e0, t, p, (t & 7) == 0);
        p ^= 1;
        e0 = e1; e1 = e2; e2 = e3; e3 = e4;
        e4 = e5; e5 = e6; e6 = e7; e7 = nn;
    }
    // final buffer parity: lim steps total from parity 0
    const int pf = lim & 1;

    // (last step ended with __syncthreads; u_sh[pf] is visible)

    // log_Z = C + log(sum u)   (redundant per-thread; identical result)
    float ssum = 0.f;
    {
        const float* up = &u_sh[pf][0];
#pragma unroll
        for (int c = 0; c < 16; c++) {
            const int fi = 4 * c + ((c >= 8) ? 4 : 0);   // padded layout
            float4 uu = *reinterpret_cast<const float4*>(up + fi);
            ssum += (uu.x + uu.y) + (uu.z + uu.w);
        }
    }
    float logz = C + __logf(ssum);

    // numerator: emission + transition scores along the gold path (masked)
    float num = 0.f;
    for (int tt = tid; tt < Tn; tt += KK) {
        int yt = y_sh[tt];
        if (yt != 0) {
            num += eb[(size_t)tt * KK + yt];
            if (tt > 0) num += tr[y_sh[tt - 1] * KK + yt];
        }
    }
#pragma unroll
    for (int o = 16; o > 0; o >>= 1) num += __shfl_xor_sync(0xffffffffu, num, o);
    if (l == 0) red2[w] = num;
    __syncthreads();
    if (tid == 0) {
        float ll = (red2[0] + red2[1]) - logz;
        atomicAdd(out, ll * negInvB);      // out pre-zeroed via memsetAsync
    }
}

extern "C" void kernel_launch(void* const* d_in, const int* in_sizes, int n_in,
                              void* d_out, int out_size)
{
    const int*   y  = (const int*)d_in[0];
    const float* em = (const float*)d_in[1];
    const float* tr = (const float*)d_in[2];

    const int Tn = 1024;                 // problem shape: B=256, T=1024, K=64
    const int B  = in_sizes[0] / Tn;

    cudaMemsetAsync(d_out, 0, sizeof(float));
    crf_forward_kernel<<<B, KK>>>(y, em, tr, Tn, -1.0f / (float)B,
                                  (float*)d_out);
}